// round 11
// baseline (speedup 1.0000x reference)
#include <cuda_runtime.h>
#include <math.h>
#include <stdint.h>

#define NB 128
#define TT 384
#define CC 256
#define HH 4
#define KVH 2
#define DD 64
#define MTOT (NB*TT)   // 49152

// Scratch (static device globals — no allocations). tf32 payloads stored as
// raw bit patterns inside float arrays.
// k-dim of GEMM operands is block-permuted: within each 16-wide block,
// element with original index i is stored at pos(i) = (i&3)*4 + (i>>2)
// (4x4 transpose, an involution). This makes each thread's 4 needed k-values
// {tg, tg+4, tg+8, tg+12} one contiguous float4 in smem.
__device__ float g_Q[NB*HH*TT*DD];    // [B,H,T,D]   tf32 bits (d natural)
__device__ float g_K[NB*KVH*TT*DD];   // [B,KV,T,D]  tf32 bits (d natural)
__device__ float g_V[NB*KVH*TT*DD];   // [B,KV,T,D]  tf32 bits
__device__ float g_Y[NB*TT*CC];       // [B*T, C]    tf32 bits, C block-permuted
__device__ float g_Xt[MTOT*CC];       // x tf32, C block-permuted
__device__ float g_WT[768*256];       // transposed weights [n][k], k permuted:
                                      // rows 0-255 WqT, 256-383 WkT,
                                      // 384-511 WvT, 512-767 WoT

// ---------------------------------------------------------------------------
// tf32 helpers
// ---------------------------------------------------------------------------
__device__ __forceinline__ uint32_t f2tf32(float x) {
    uint32_t u;
    asm("cvt.rna.tf32.f32 %0, %1;" : "=r"(u) : "f"(x));
    return u;
}
__device__ __forceinline__ float f2tf32f(float x) {
    return __uint_as_float(f2tf32(x));
}

__device__ __forceinline__ void mma_tf32(float* d, const uint32_t* a, const uint32_t* b) {
    asm volatile(
        "mma.sync.aligned.m16n8k8.row.col.f32.tf32.tf32.f32 "
        "{%0,%1,%2,%3}, {%4,%5,%6,%7}, {%8,%9}, {%0,%1,%2,%3};"
        : "+f"(d[0]), "+f"(d[1]), "+f"(d[2]), "+f"(d[3])
        : "r"(a[0]), "r"(a[1]), "r"(a[2]), "r"(a[3]),
          "r"(b[0]), "r"(b[1]));
}

__device__ __forceinline__ void cp16(uint32_t smem_addr, const float* g) {
    asm volatile("cp.async.cg.shared.global [%0], [%1], 16;\n"
                 :: "r"(smem_addr), "l"(g));
}

// ---------------------------------------------------------------------------
// Kernel 0: pre-convert + permute x, transpose + permute weights.
// ---------------------------------------------------------------------------
__global__ __launch_bounds__(256) void prepass_kernel(
    const float* __restrict__ x,  const float* __restrict__ Wq,
    const float* __restrict__ Wk, const float* __restrict__ Wv,
    const float* __restrict__ Wo)
{
    const int stride = gridDim.x * blockDim.x;
    const int t0 = blockIdx.x * blockDim.x + threadIdx.x;

    // x -> g_Xt : out float4 (m, blk, jj) holds orig k = blk*16 + {jj, jj+4, jj+8, jj+12}
    const int N4x = (MTOT * CC) / 4;
    for (int idx = t0; idx < N4x; idx += stride) {
        int m   = idx >> 6;
        int jg  = idx & 63;
        int blk = jg >> 2, jj = jg & 3;
        const float* src = &x[m * 256 + blk * 16 + jj];
        float4 v;
        v.x = f2tf32f(src[0]);
        v.y = f2tf32f(src[4]);
        v.z = f2tf32f(src[8]);
        v.w = f2tf32f(src[12]);
        reinterpret_cast<float4*>(g_Xt)[m * 64 + blk * 4 + jj] = v;
    }

    // weights -> g_WT [n][k] transposed, k permuted
    for (int idx = t0; idx < 768 * 64; idx += stride) {
        int n   = idx >> 6;
        int jg  = idx & 63;
        int blk = jg >> 2, jj = jg & 3;
        const float* src; int col, ldn;
        if (n < 256)      { src = Wq; col = n;       ldn = 256; }
        else if (n < 384) { src = Wk; col = n - 256; ldn = 128; }
        else if (n < 512) { src = Wv; col = n - 384; ldn = 128; }
        else              { src = Wo; col = n - 512; ldn = 256; }
        int kb = blk * 16 + jj;
        float4 v;
        v.x = f2tf32f(src[(kb     ) * ldn + col]);
        v.y = f2tf32f(src[(kb +  4) * ldn + col]);
        v.z = f2tf32f(src[(kb +  8) * ldn + col]);
        v.w = f2tf32f(src[(kb + 12) * ldn + col]);
        reinterpret_cast<float4*>(g_WT)[n * 64 + blk * 4 + jj] = v;
    }
}

// ---------------------------------------------------------------------------
// tf32 GEMM, block tile 128x128, K=256 in 16-wide steps, 3-stage cp.async.
// A and B tiles are both [128 rows][16 k] (k permuted) -> smem stride 20.
// Fragment loads: LDS.128 only (12 per warp per K-step vs 48 scalar before).
// MODE 0: qkv projection + RoPE epilogue;  MODE 1: A=g_Y, B=WoT -> out
// ---------------------------------------------------------------------------
#define STG 5120      // floats per stage: A 2560 + B 2560
#define NK  16

template<int MODE>
__global__ __launch_bounds__(256, 2) void gemm_tf32_kernel(float* __restrict__ out)
{
    extern __shared__ char smraw[];
    float* smf = (float*)smraw;
    const uint32_t smem_u32 = (uint32_t)__cvta_generic_to_shared(smraw);

    const float* A = (MODE == 1) ? (const float*)g_Y : (const float*)g_Xt;
    const float* W = (MODE == 1) ? (const float*)g_WT + 512 * 256
                                 : (const float*)g_WT;

    const int m0 = blockIdx.x * 128;
    const int n0 = blockIdx.y * 128;

    const int tid  = threadIdx.x;
    const int lane = tid & 31;
    const int wid  = tid >> 5;
    const int wm   = wid >> 2;
    const int wn   = wid & 3;
    const int grp  = lane >> 2;
    const int tg   = lane & 3;

    const int row0 = tid >> 2;          // +u*64
    const int seg  = (tid & 3) << 2;    // 0,4,8,12

    float acc[4][4][4];
    #pragma unroll
    for (int i = 0; i < 4; i++)
        #pragma unroll
        for (int j = 0; j < 4; j++)
            #pragma unroll
            for (int r = 0; r < 4; r++) acc[i][j][r] = 0.f;

    auto issue = [&](int kt, int s) {
        const int k0 = kt * 16;
        const uint32_t sA = smem_u32 + s * STG * 4;
        const uint32_t sB = sA + 2560 * 4;
        #pragma unroll
        for (int u = 0; u < 2; u++) {
            int r = row0 + u * 64;
            cp16(sA + (r * 20 + seg) * 4, &A[(m0 + r) * CC + k0 + seg]);
            cp16(sB + (r * 20 + seg) * 4, &W[(n0 + r) * CC + k0 + seg]);
        }
        asm volatile("cp.async.commit_group;\n" ::);
    };

    issue(0, 0);
    issue(1, 1);

    for (int kt = 0; kt < NK; kt++) {
        if (kt < NK - 1) asm volatile("cp.async.wait_group 1;\n" ::);
        else             asm volatile("cp.async.wait_group 0;\n" ::);
        __syncthreads();

        if (kt + 2 < NK) issue(kt + 2, (kt + 2) % 3);

        const uint32_t* Au = (const uint32_t*)(smf + (kt % 3) * STG);
        const uint32_t* Bu = Au + 2560;

        // B fragments: one LDS.128 per j covers both kk-halves
        uint4 bq[4];
        #pragma unroll
        for (int j = 0; j < 4; j++)
            bq[j] = *reinterpret_cast<const uint4*>(
                        &Bu[(wn * 32 + j * 8 + grp) * 20 + tg * 4]);

        #pragma unroll
        for (int i = 0; i < 4; i++) {
            int mb = wm * 64 + i * 16 + grp;
            uint4 alo = *reinterpret_cast<const uint4*>(&Au[(mb    ) * 20 + tg * 4]);
            uint4 ahi = *reinterpret_cast<const uint4*>(&Au[(mb + 8) * 20 + tg * 4]);
            uint32_t a0[4] = {alo.x, ahi.x, alo.y, ahi.y};   // kk = 0
            uint32_t a1[4] = {alo.z, ahi.z, alo.w, ahi.w};   // kk = 8
            #pragma unroll
            for (int j = 0; j < 4; j++) {
                uint32_t b0[2] = {bq[j].x, bq[j].y};
                mma_tf32(acc[i][j], a0, b0);
                uint32_t b1[2] = {bq[j].z, bq[j].w};
                mma_tf32(acc[i][j], a1, b1);
            }
        }
    }
    __syncthreads();

    float* Cs = smf;   // [64][132]

    #pragma unroll
    for (int half = 0; half < 2; half++) {
        if (wm == half) {
            #pragma unroll
            for (int i = 0; i < 4; i++)
                #pragma unroll
                for (int j = 0; j < 4; j++)
                    #pragma unroll
                    for (int rr = 0; rr < 4; rr++) {
                        int row = i * 16 + grp + ((rr >> 1) << 3);
                        int col = wn * 32 + j * 8 + tg * 2 + (rr & 1);
                        Cs[row * 132 + col] = acc[i][j][rr];
                    }
        }
        __syncthreads();

        const int r    = tid >> 2;
        const int cseg = (tid & 3) << 5;
        const int gm   = m0 + half * 64 + r;
        const float* Crow = &Cs[r * 132];

        if (MODE == 1) {
            float* dst = &out[gm * CC + n0 + cseg];
            #pragma unroll
            for (int c = 0; c < 32; c += 4)
                *reinterpret_cast<float4*>(&dst[c]) =
                    *reinterpret_cast<const float4*>(&Crow[cseg + c]);
        } else {
            const int bb = gm / TT;
            const int t  = gm - bb * TT;
            const int cglob = n0 + cseg;
            if (cglob >= 384) {
                int hh = (cglob - 384) >> 6;
                float* dst = &g_V[((bb * KVH + hh) * TT + t) * DD + (cglob & 63)];
                #pragma unroll
                for (int c = 0; c < 32; c += 4) {
                    float4 v = *reinterpret_cast<const float4*>(&Crow[cseg + c]);
                    v.x = f2tf32f(v.x); v.y = f2tf32f(v.y);
                    v.z = f2tf32f(v.z); v.w = f2tf32f(v.w);
                    *reinterpret_cast<float4*>(&dst[c]) = v;
                }
            } else {
                float* dst;
                if (cglob < 256) dst = &g_Q[((bb * HH  + (cglob >> 6)       ) * TT + t) * DD];
                else             dst = &g_K[((bb * KVH + ((cglob - 256) >> 6)) * TT + t) * DD];
                const int dhalf = cglob & 32;
                const float tf = (float)t;
                #pragma unroll
                for (int c = 0; c < 32; c += 4) {
                    float4 v;
                    float* vp = &v.x;
                    #pragma unroll
                    for (int e = 0; e < 4; e++) {
                        int cc = c + e;
                        float invf = exp2f(-0.41524101186f * (float)cc);
                        float ang = tf * invf;
                        float sn, cs;
                        sincosf(ang, &sn, &cs);
                        float val;
                        if (dhalf == 0)
                            val = Crow[cseg + cc] * cs - Crow[cseg + 32 + cc] * sn;
                        else
                            val = Crow[cseg + cc] * cs + Crow[cseg - 32 + cc] * sn;
                        vp[e] = f2tf32f(val);
                    }
                    *reinterpret_cast<float4*>(&dst[dhalf + c]) = v;
                }
            }
        }
        __syncthreads();
    }
}

// ---------------------------------------------------------------------------
// Kernel 2: causal flash attention with tf32 mma (as R9, double-buffered
// cp.async K/V). Only change: final Y write permutes columns within each
// 16-block of C so the proj GEMM can LDS.128 its A fragments.
// ---------------------------------------------------------------------------
__global__ __launch_bounds__(128) void attn_mma_kernel()
{
    extern __shared__ uint32_t sm[];
    uint32_t* Qs  = sm;                      // 64*68
    uint32_t* Kst = Qs + 64 * 68;            // 2 stages
    uint32_t* Vst = Kst + 2 * 64 * 68;       // 2 stages
    uint32_t* Ps  = Vst + 2 * 64 * 68;
    float* sm_corr = (float*)(Ps + 64 * 68);
    float* sm_l    = sm_corr + 64;

    const uint32_t smem_u32 = (uint32_t)__cvta_generic_to_shared(sm);
    const uint32_t Ks_u32 = smem_u32 + (64 * 68) * 4;
    const uint32_t Vs_u32 = Ks_u32 + (2 * 64 * 68) * 4;

    const int qt = gridDim.x - 1 - blockIdx.x;
    const int h  = blockIdx.y;
    const int b  = blockIdx.z;
    const int kv = h >> 1;
    const int tid  = threadIdx.x;
    const int lane = tid & 31;
    const int wid  = tid >> 5;
    const int grp  = lane >> 2;
    const int tg   = lane & 3;
    const int wrow = wid * 16;

    const float* Qg = &g_Q[((b * HH + h) * TT + qt * 64) * DD];
    const float* Kg = &g_K[((b * KVH + kv) * TT) * DD];
    const float* Vg = &g_V[((b * KVH + kv) * TT) * DD];

    const int crow0 = tid >> 4;
    const int cseg  = (tid & 15) << 2;

    auto issueKV = [&](int kt, int s) {
        const uint32_t sK = Ks_u32 + s * (64 * 68) * 4;
        const uint32_t sV = Vs_u32 + s * (64 * 68) * 4;
        const float* Kt = Kg + kt * 64 * DD;
        const float* Vt = Vg + kt * 64 * DD;
        #pragma unroll
        for (int u = 0; u < 8; u++) {
            int r = crow0 + u * 8;
            cp16(sK + (r * 68 + cseg) * 4, &Kt[r * 64 + cseg]);
            cp16(sV + (r * 68 + cseg) * 4, &Vt[r * 64 + cseg]);
        }
        asm volatile("cp.async.commit_group;\n" ::);
    };

    #pragma unroll
    for (int u = 0; u < 8; u++) {
        int r = crow0 + u * 8;
        cp16(smem_u32 + (r * 68 + cseg) * 4, &Qg[r * 64 + cseg]);
    }
    issueKV(0, 0);

    float m0 = -1e30f, m1 = -1e30f;
    float l0 = 0.f,   l1 = 0.f;
    float acc_o[8][4];
    #pragma unroll
    for (int j = 0; j < 8; j++)
        #pragma unroll
        for (int e = 0; e < 4; e++) acc_o[j][e] = 0.f;

    for (int kt = 0; kt <= qt; kt++) {
        asm volatile("cp.async.wait_group 0;\n" ::);
        __syncthreads();
        if (kt < qt) issueKV(kt + 1, (kt + 1) & 1);

        const uint32_t* Ks = Kst + (kt & 1) * (64 * 68);
        const uint32_t* Vs = Vst + (kt & 1) * (64 * 68);

        float s[8][4];
        #pragma unroll
        for (int j = 0; j < 8; j++)
            #pragma unroll
            for (int e = 0; e < 4; e++) s[j][e] = 0.f;

        #pragma unroll
        for (int kk = 0; kk < 64; kk += 8) {
            uint32_t a[4];
            a[0] = Qs[(wrow + grp    ) * 68 + kk + tg    ];
            a[1] = Qs[(wrow + grp + 8) * 68 + kk + tg    ];
            a[2] = Qs[(wrow + grp    ) * 68 + kk + tg + 4];
            a[3] = Qs[(wrow + grp + 8) * 68 + kk + tg + 4];
            #pragma unroll
            for (int j = 0; j < 8; j++) {
                uint32_t bf[2];
                bf[0] = Ks[(j * 8 + grp) * 68 + kk + tg    ];
                bf[1] = Ks[(j * 8 + grp) * 68 + kk + tg + 4];
                mma_tf32(s[j], a, bf);
            }
        }

        const int row0 = qt * 64 + wrow + grp;
        const int row1 = row0 + 8;
        float mx0 = -1e30f, mx1 = -1e30f;
        #pragma unroll
        for (int j = 0; j < 8; j++) {
            #pragma unroll
            for (int e = 0; e < 4; e++) {
                float v = s[j][e] * 0.125f;
                if (kt == qt) {
                    int col = kt * 64 + j * 8 + 2 * tg + (e & 1);
                    int row = (e < 2) ? row0 : row1;
                    if (col > row) v = -1e30f;
                }
                s[j][e] = v;
            }
            mx0 = fmaxf(mx0, fmaxf(s[j][0], s[j][1]));
            mx1 = fmaxf(mx1, fmaxf(s[j][2], s[j][3]));
        }
        mx0 = fmaxf(mx0, __shfl_xor_sync(0xffffffffu, mx0, 1));
        mx0 = fmaxf(mx0, __shfl_xor_sync(0xffffffffu, mx0, 2));
        mx1 = fmaxf(mx1, __shfl_xor_sync(0xffffffffu, mx1, 1));
        mx1 = fmaxf(mx1, __shfl_xor_sync(0xffffffffu, mx1, 2));

        float mn0 = fmaxf(m0, mx0), mn1 = fmaxf(m1, mx1);
        float c0 = __expf(m0 - mn0), c1 = __expf(m1 - mn1);
        m0 = mn0; m1 = mn1;
        l0 *= c0; l1 *= c1;

        #pragma unroll
        for (int j = 0; j < 8; j++) {
            uint32_t p0 = f2tf32(__expf(s[j][0] - mn0));
            uint32_t p1 = f2tf32(__expf(s[j][1] - mn0));
            uint32_t p2 = f2tf32(__expf(s[j][2] - mn1));
            uint32_t p3 = f2tf32(__expf(s[j][3] - mn1));
            l0 += __uint_as_float(p0) + __uint_as_float(p1);
            l1 += __uint_as_float(p2) + __uint_as_float(p3);
            Ps[(wrow + grp    ) * 68 + j * 8 + 2 * tg    ] = p0;
            Ps[(wrow + grp    ) * 68 + j * 8 + 2 * tg + 1] = p1;
            Ps[(wrow + grp + 8) * 68 + j * 8 + 2 * tg    ] = p2;
            Ps[(wrow + grp + 8) * 68 + j * 8 + 2 * tg + 1] = p3;
        }
        if (tg == 0) {
            sm_corr[wrow + grp    ] = c0;
            sm_corr[wrow + grp + 8] = c1;
        }
        __syncthreads();

        #pragma unroll
        for (int j = 0; j < 8; j++) {
            float cc0 = sm_corr[j * 8 + 2 * tg    ];
            float cc1 = sm_corr[j * 8 + 2 * tg + 1];
            acc_o[j][0] *= cc0; acc_o[j][1] *= cc1;
            acc_o[j][2] *= cc0; acc_o[j][3] *= cc1;
        }
        #pragma unroll
        for (int kk = 0; kk < 64; kk += 8) {
            uint32_t a[4];
            a[0] = Vs[(kk + tg    ) * 68 + wrow + grp    ];
            a[1] = Vs[(kk + tg    ) * 68 + wrow + grp + 8];
            a[2] = Vs[(kk + tg + 4) * 68 + wrow + grp    ];
            a[3] = Vs[(kk + tg + 4) * 68 + wrow + grp + 8];
            #pragma unroll
            for (int j = 0; j < 8; j++) {
                uint32_t bf[2];
                bf[0] = Ps[(j * 8 + grp) * 68 + kk + tg    ];
                bf[1] = Ps[(j * 8 + grp) * 68 + kk + tg + 4];
                mma_tf32(acc_o[j], a, bf);
            }
        }
        __syncthreads();
    }

    l0 += __shfl_xor_sync(0xffffffffu, l0, 1);
    l0 += __shfl_xor_sync(0xffffffffu, l0, 2);
    l1 += __shfl_xor_sync(0xffffffffu, l1, 1);
    l1 += __shfl_xor_sync(0xffffffffu, l1, 2);
    if (tg == 0) {
        sm_l[wrow + grp    ] = l0;
        sm_l[wrow + grp + 8] = l1;
    }
    __syncthreads();

    // write O as tf32 bits with block-permuted columns:
    // column (h*64 + d), in-block idx d&15; d0 = wrow+grp -> pos = pos(grp),
    // d1 = d0+8 -> pos(grp+8) = pos(grp)+2.
    float* Yb = &g_Y[((size_t)(b * TT + qt * 64)) * CC + h * DD];
    const int pg = (grp & 3) * 4 + (grp >> 2);
    #pragma unroll
    for (int j = 0; j < 8; j++) {
        int q0 = j * 8 + 2 * tg, q1 = q0 + 1;
        float i0 = 1.f / sm_l[q0];
        float i1 = 1.f / sm_l[q1];
        int c0 = wrow + pg;
        Yb[q0 * CC + c0    ] = f2tf32f(acc_o[j][0] * i0);
        Yb[q1 * CC + c0    ] = f2tf32f(acc_o[j][1] * i1);
        Yb[q0 * CC + c0 + 2] = f2tf32f(acc_o[j][2] * i0);
        Yb[q1 * CC + c0 + 2] = f2tf32f(acc_o[j][3] * i1);
    }
}

// ---------------------------------------------------------------------------
extern "C" void kernel_launch(void* const* d_in, const int* in_sizes, int n_in,
                              void* d_out, int out_size)
{
    const float* x  = (const float*)d_in[0];
    const float* Wq = (const float*)d_in[1];
    const float* Wk = (const float*)d_in[2];
    const float* Wv = (const float*)d_in[3];
    const float* Wo = (const float*)d_in[4];
    float* out = (float*)d_out;

    const int smem_gemm = 3 * STG * 4;                       // 61440
    const int smem_attn = (6 * 64 * 68) * 4 + 2 * 64 * 4;    // 104960 + 512
    static bool attr_done = false;
    if (!attr_done) {
        cudaFuncSetAttribute(gemm_tf32_kernel<0>,
                             cudaFuncAttributeMaxDynamicSharedMemorySize, smem_gemm);
        cudaFuncSetAttribute(gemm_tf32_kernel<1>,
                             cudaFuncAttributeMaxDynamicSharedMemorySize, smem_gemm);
        cudaFuncSetAttribute(attn_mma_kernel,
                             cudaFuncAttributeMaxDynamicSharedMemorySize, smem_attn);
        attr_done = true;
    }

    prepass_kernel<<<1024, 256>>>(x, Wq, Wk, Wv, Wo);

    dim3 g1(MTOT / 128, 512 / 128);
    gemm_tf32_kernel<0><<<g1, 256, smem_gemm>>>(nullptr);

    dim3 g2(TT / 64, HH, NB);
    attn_mma_kernel<<<g2, 128, smem_attn>>>();

    dim3 g3(MTOT / 128, CC / 128);
    gemm_tf32_kernel<1><<<g3, 256, smem_gemm>>>(out);
}

// round 13
// speedup vs baseline: 1.7781x; 1.7781x over previous
#include <cuda_runtime.h>
#include <math.h>
#include <stdint.h>

#define NB 128
#define TT 384
#define CC 256
#define HH 4
#define KVH 2
#define DD 64
#define MTOT (NB*TT)   // 49152

// Scratch (static device globals — no allocations). tf32 payloads stored as
// raw bit patterns inside float arrays.
__device__ float g_Q[NB*HH*TT*DD];    // [B,H,T,D]   tf32 bits
__device__ float g_K[NB*KVH*TT*DD];   // [B,KV,T,D]  tf32 bits
__device__ float g_V[NB*KVH*TT*DD];   // [B,KV,T,D]  tf32 bits
__device__ float g_Y[NB*TT*CC];       // [B*T, C]    tf32 bits
__device__ float g_Wt[256*512 + 256*256]; // Wq|Wk|Wv|Wo pre-rounded tf32 bits
#define WQ_OFF 0
#define WK_OFF 65536
#define WV_OFF 98304
#define WO_OFF 131072

// ---------------------------------------------------------------------------
// tf32 helpers
// ---------------------------------------------------------------------------
__device__ __forceinline__ uint32_t f2tf32(float x) {
    uint32_t u;
    asm("cvt.rna.tf32.f32 %0, %1;" : "=r"(u) : "f"(x));
    return u;
}
__device__ __forceinline__ float f2tf32f(float x) {
    return __uint_as_float(f2tf32(x));
}

__device__ __forceinline__ void mma_tf32(float* d, const uint32_t* a, const uint32_t* b) {
    asm volatile(
        "mma.sync.aligned.m16n8k8.row.col.f32.tf32.tf32.f32 "
        "{%0,%1,%2,%3}, {%4,%5,%6,%7}, {%8,%9}, {%0,%1,%2,%3};"
        : "+f"(d[0]), "+f"(d[1]), "+f"(d[2]), "+f"(d[3])
        : "r"(a[0]), "r"(a[1]), "r"(a[2]), "r"(a[3]),
          "r"(b[0]), "r"(b[1]));
}

__device__ __forceinline__ void cp16(uint32_t smem_addr, const float* g) {
    asm volatile("cp.async.cg.shared.global [%0], [%1], 16;\n"
                 :: "r"(smem_addr), "l"(g));
}

// ---------------------------------------------------------------------------
// Kernel 0: pre-convert weights only (192 KB total — ~2 us).
// ---------------------------------------------------------------------------
__device__ __forceinline__ uint4 cvt4(float4 v) {
    uint4 u;
    u.x = f2tf32(v.x); u.y = f2tf32(v.y);
    u.z = f2tf32(v.z); u.w = f2tf32(v.w);
    return u;
}

__global__ __launch_bounds__(256) void prepass_kernel(
    const float* __restrict__ Wq, const float* __restrict__ Wk,
    const float* __restrict__ Wv, const float* __restrict__ Wo)
{
    const int stride = gridDim.x * blockDim.x;
    const int i0 = blockIdx.x * blockDim.x + threadIdx.x;
    uint4* Wt = reinterpret_cast<uint4*>(g_Wt);
    for (int i = i0; i < 16384; i += stride)
        Wt[WQ_OFF/4 + i] = cvt4(reinterpret_cast<const float4*>(Wq)[i]);
    for (int i = i0; i < 8192; i += stride)
        Wt[WK_OFF/4 + i] = cvt4(reinterpret_cast<const float4*>(Wk)[i]);
    for (int i = i0; i < 8192; i += stride)
        Wt[WV_OFF/4 + i] = cvt4(reinterpret_cast<const float4*>(Wv)[i]);
    for (int i = i0; i < 16384; i += stride)
        Wt[WO_OFF/4 + i] = cvt4(reinterpret_cast<const float4*>(Wo)[i]);
}

// ---------------------------------------------------------------------------
// tf32 GEMM, block tile 128x128, K=256 in 16-wide steps, 3-stage cp.async
// pipeline. Scalar LDS fragment loads (conflict-free stride 20/136).
// MODE 0: A = x (raw fp32; cvt at A-fragment load), B = g_Wt bits. +RoPE epi.
// MODE 1: A = g_Y (tf32 bits, no cvt), B = Wo bits -> out fp32.
// ---------------------------------------------------------------------------
#define STG 4736
#define NK  16

template<int MODE>
__global__ __launch_bounds__(256, 2) void gemm_tf32_kernel(
    const float* __restrict__ Ain, float* __restrict__ out)
{
    extern __shared__ char smraw[];
    float* smf = (float*)smraw;
    const uint32_t smem_u32 = (uint32_t)__cvta_generic_to_shared(smraw);

    const float* A = (MODE == 1) ? (const float*)g_Y : Ain;

    const int m0 = blockIdx.x * 128;
    const int n0 = blockIdx.y * 128;

    const float* W; int ldb, noff;
    if (MODE == 1)     { W = g_Wt + WO_OFF; ldb = 256; noff = n0;       }
    else if (n0 < 256) { W = g_Wt + WQ_OFF; ldb = 256; noff = n0;       }
    else if (n0 < 384) { W = g_Wt + WK_OFF; ldb = 128; noff = n0 - 256; }
    else               { W = g_Wt + WV_OFF; ldb = 128; noff = n0 - 384; }

    const int tid  = threadIdx.x;
    const int lane = tid & 31;
    const int wid  = tid >> 5;
    const int wm   = wid >> 2;
    const int wn   = wid & 3;
    const int grp  = lane >> 2;
    const int tg   = lane & 3;

    const int a_row0 = tid >> 2;
    const int a_seg  = (tid & 3) << 2;
    const int b_row0 = tid >> 5;
    const int b_off  = (tid & 31) << 2;

    float acc[4][4][4];
    #pragma unroll
    for (int i = 0; i < 4; i++)
        #pragma unroll
        for (int j = 0; j < 4; j++)
            #pragma unroll
            for (int r = 0; r < 4; r++) acc[i][j][r] = 0.f;

    auto issue = [&](int kt, int s) {
        const int k0 = kt * 16;
        const uint32_t sA = smem_u32 + s * STG * 4;
        const uint32_t sB = sA + 2560 * 4;
        #pragma unroll
        for (int u = 0; u < 2; u++) {
            int row = a_row0 + u * 64;
            cp16(sA + (row * 20 + a_seg) * 4, &A[(m0 + row) * CC + k0 + a_seg]);
        }
        #pragma unroll
        for (int u = 0; u < 2; u++) {
            int row = b_row0 + u * 8;
            cp16(sB + (row * 136 + b_off) * 4, &W[(k0 + row) * ldb + noff + b_off]);
        }
        asm volatile("cp.async.commit_group;\n" ::);
    };

    // A-fragment element: MODE 0 converts the raw fp32 to tf32 here (fma pipe
    // is nearly idle); MODE 1 reads pre-rounded bits.
    auto ldA = [&](const uint32_t* Au, int idx) -> uint32_t {
        if (MODE == 0) return f2tf32(__uint_as_float(Au[idx]));
        else           return Au[idx];
    };

    issue(0, 0);
    issue(1, 1);

    for (int kt = 0; kt < NK; kt++) {
        if (kt < NK - 1) asm volatile("cp.async.wait_group 1;\n" ::);
        else             asm volatile("cp.async.wait_group 0;\n" ::);
        __syncthreads();

        if (kt + 2 < NK) issue(kt + 2, (kt + 2) % 3);

        const uint32_t* Au = (const uint32_t*)(smf + (kt % 3) * STG);
        const uint32_t* Bu = Au + 2560;

        #pragma unroll
        for (int kk = 0; kk < 16; kk += 8) {
            uint32_t af[4][4];
            #pragma unroll
            for (int i = 0; i < 4; i++) {
                int mb = wm * 64 + i * 16 + grp;
                af[i][0] = ldA(Au, (mb    ) * 20 + kk + tg    );
                af[i][1] = ldA(Au, (mb + 8) * 20 + kk + tg    );
                af[i][2] = ldA(Au, (mb    ) * 20 + kk + tg + 4);
                af[i][3] = ldA(Au, (mb + 8) * 20 + kk + tg + 4);
            }
            uint32_t bf[4][2];
            #pragma unroll
            for (int j = 0; j < 4; j++) {
                int nb = wn * 32 + j * 8 + grp;
                bf[j][0] = Bu[(kk + tg    ) * 136 + nb];
                bf[j][1] = Bu[(kk + tg + 4) * 136 + nb];
            }
            #pragma unroll
            for (int i = 0; i < 4; i++)
                #pragma unroll
                for (int j = 0; j < 4; j++)
                    mma_tf32(acc[i][j], af[i], bf[j]);
        }
    }
    __syncthreads();

    float* Cs = smf;   // [64][132]

    #pragma unroll
    for (int half = 0; half < 2; half++) {
        if (wm == half) {
            #pragma unroll
            for (int i = 0; i < 4; i++)
                #pragma unroll
                for (int j = 0; j < 4; j++)
                    #pragma unroll
                    for (int rr = 0; rr < 4; rr++) {
                        int row = i * 16 + grp + ((rr >> 1) << 3);
                        int col = wn * 32 + j * 8 + tg * 2 + (rr & 1);
                        Cs[row * 132 + col] = acc[i][j][rr];
                    }
        }
        __syncthreads();

        const int r   = tid >> 2;
        const int seg = (tid & 3) << 5;
        const int gm  = m0 + half * 64 + r;
        const float* Crow = &Cs[r * 132];

        if (MODE == 1) {
            float* dst = &out[gm * CC + n0 + seg];
            #pragma unroll
            for (int c = 0; c < 32; c += 4)
                *reinterpret_cast<float4*>(&dst[c]) =
                    *reinterpret_cast<const float4*>(&Crow[seg + c]);
        } else {
            const int bb = gm / TT;
            const int t  = gm - bb * TT;
            const int cglob = n0 + seg;
            if (cglob >= 384) {
                // V: copy, rounded to tf32 bits
                int hh = (cglob - 384) >> 6;
                float* dst = &g_V[((bb * KVH + hh) * TT + t) * DD + (cglob & 63)];
                #pragma unroll
                for (int c = 0; c < 32; c += 4) {
                    float4 v = *reinterpret_cast<const float4*>(&Crow[seg + c]);
                    v.x = f2tf32f(v.x); v.y = f2tf32f(v.y);
                    v.z = f2tf32f(v.z); v.w = f2tf32f(v.w);
                    *reinterpret_cast<float4*>(&dst[c]) = v;
                }
            } else {
                float* dst;
                if (cglob < 256) dst = &g_Q[((bb * HH  + (cglob >> 6)       ) * TT + t) * DD];
                else             dst = &g_K[((bb * KVH + ((cglob - 256) >> 6)) * TT + t) * DD];
                const int dhalf = cglob & 32;
                const float tf = (float)t;
                #pragma unroll
                for (int c = 0; c < 32; c += 4) {
                    float4 v;
                    float* vp = &v.x;
                    #pragma unroll
                    for (int e = 0; e < 4; e++) {
                        int cc = c + e;
                        float invf = exp2f(-0.41524101186f * (float)cc);
                        float ang = tf * invf;
                        float sn, cs;
                        sincosf(ang, &sn, &cs);
                        float val;
                        if (dhalf == 0)
                            val = Crow[seg + cc] * cs - Crow[seg + 32 + cc] * sn;
                        else
                            val = Crow[seg + cc] * cs + Crow[seg - 32 + cc] * sn;
                        vp[e] = f2tf32f(val);
                    }
                    *reinterpret_cast<float4*>(&dst[dhalf + c]) = v;
                }
            }
        }
        __syncthreads();
    }
}

// ---------------------------------------------------------------------------
// Kernel 2: causal flash attention with tf32 mma.
// Q/K/V arrive pre-rounded tf32 -> loads are cp.async raw copies.
// K/V double-buffered: next tile streams in during current tile's mma work.
// ---------------------------------------------------------------------------
__global__ __launch_bounds__(128) void attn_mma_kernel()
{
    extern __shared__ uint32_t sm[];
    uint32_t* Qs  = sm;                      // 64*68
    uint32_t* Kst = Qs + 64 * 68;            // 2 stages
    uint32_t* Vst = Kst + 2 * 64 * 68;       // 2 stages
    uint32_t* Ps  = Vst + 2 * 64 * 68;
    float* sm_corr = (float*)(Ps + 64 * 68);
    float* sm_l    = sm_corr + 64;

    const uint32_t smem_u32 = (uint32_t)__cvta_generic_to_shared(sm);
    const uint32_t Ks_u32 = smem_u32 + (64 * 68) * 4;
    const uint32_t Vs_u32 = Ks_u32 + (2 * 64 * 68) * 4;

    const int qt = gridDim.x - 1 - blockIdx.x;
    const int h  = blockIdx.y;
    const int b  = blockIdx.z;
    const int kv = h >> 1;
    const int tid  = threadIdx.x;
    const int lane = tid & 31;
    const int wid  = tid >> 5;
    const int grp  = lane >> 2;
    const int tg   = lane & 3;
    const int wrow = wid * 16;

    const float* Qg = &g_Q[((b * HH + h) * TT + qt * 64) * DD];
    const float* Kg = &g_K[((b * KVH + kv) * TT) * DD];
    const float* Vg = &g_V[((b * KVH + kv) * TT) * DD];

    const int crow0 = tid >> 4;
    const int cseg  = (tid & 15) << 2;

    auto issueKV = [&](int kt, int s) {
        const uint32_t sK = Ks_u32 + s * (64 * 68) * 4;
        const uint32_t sV = Vs_u32 + s * (64 * 68) * 4;
        const float* Kt = Kg + kt * 64 * DD;
        const float* Vt = Vg + kt * 64 * DD;
        #pragma unroll
        for (int u = 0; u < 8; u++) {
            int r = crow0 + u * 8;
            cp16(sK + (r * 68 + cseg) * 4, &Kt[r * 64 + cseg]);
            cp16(sV + (r * 68 + cseg) * 4, &Vt[r * 64 + cseg]);
        }
        asm volatile("cp.async.commit_group;\n" ::);
    };

    #pragma unroll
    for (int u = 0; u < 8; u++) {
        int r = crow0 + u * 8;
        cp16(smem_u32 + (r * 68 + cseg) * 4, &Qg[r * 64 + cseg]);
    }
    issueKV(0, 0);

    float m0 = -1e30f, m1 = -1e30f;
    float l0 = 0.f,   l1 = 0.f;
    float acc_o[8][4];
    #pragma unroll
    for (int j = 0; j < 8; j++)
        #pragma unroll
        for (int e = 0; e < 4; e++) acc_o[j][e] = 0.f;

    for (int kt = 0; kt <= qt; kt++) {
        asm volatile("cp.async.wait_group 0;\n" ::);
        __syncthreads();
        if (kt < qt) issueKV(kt + 1, (kt + 1) & 1);

        const uint32_t* Ks = Kst + (kt & 1) * (64 * 68);
        const uint32_t* Vs = Vst + (kt & 1) * (64 * 68);

        // ---- S = Q K^T ----
        float s[8][4];
        #pragma unroll
        for (int j = 0; j < 8; j++)
            #pragma unroll
            for (int e = 0; e < 4; e++) s[j][e] = 0.f;

        #pragma unroll
        for (int kk = 0; kk < 64; kk += 8) {
            uint32_t a[4];
            a[0] = Qs[(wrow + grp    ) * 68 + kk + tg    ];
            a[1] = Qs[(wrow + grp + 8) * 68 + kk + tg    ];
            a[2] = Qs[(wrow + grp    ) * 68 + kk + tg + 4];
            a[3] = Qs[(wrow + grp + 8) * 68 + kk + tg + 4];
            #pragma unroll
            for (int j = 0; j < 8; j++) {
                uint32_t bf[2];
                bf[0] = Ks[(j * 8 + grp) * 68 + kk + tg    ];
                bf[1] = Ks[(j * 8 + grp) * 68 + kk + tg + 4];
                mma_tf32(s[j], a, bf);
            }
        }

        // ---- scale, causal mask, online softmax ----
        const int row0 = qt * 64 + wrow + grp;
        const int row1 = row0 + 8;
        float mx0 = -1e30f, mx1 = -1e30f;
        #pragma unroll
        for (int j = 0; j < 8; j++) {
            #pragma unroll
            for (int e = 0; e < 4; e++) {
                float v = s[j][e] * 0.125f;
                if (kt == qt) {
                    int col = kt * 64 + j * 8 + 2 * tg + (e & 1);
                    int row = (e < 2) ? row0 : row1;
                    if (col > row) v = -1e30f;
                }
                s[j][e] = v;
            }
            mx0 = fmaxf(mx0, fmaxf(s[j][0], s[j][1]));
            mx1 = fmaxf(mx1, fmaxf(s[j][2], s[j][3]));
        }
        mx0 = fmaxf(mx0, __shfl_xor_sync(0xffffffffu, mx0, 1));
        mx0 = fmaxf(mx0, __shfl_xor_sync(0xffffffffu, mx0, 2));
        mx1 = fmaxf(mx1, __shfl_xor_sync(0xffffffffu, mx1, 1));
        mx1 = fmaxf(mx1, __shfl_xor_sync(0xffffffffu, mx1, 2));

        float mn0 = fmaxf(m0, mx0), mn1 = fmaxf(m1, mx1);
        float c0 = __expf(m0 - mn0), c1 = __expf(m1 - mn1);
        m0 = mn0; m1 = mn1;
        l0 *= c0; l1 *= c1;

        #pragma unroll
        for (int j = 0; j < 8; j++) {
            uint32_t p0 = f2tf32(__expf(s[j][0] - mn0));
            uint32_t p1 = f2tf32(__expf(s[j][1] - mn0));
            uint32_t p2 = f2tf32(__expf(s[j][2] - mn1));
            uint32_t p3 = f2tf32(__expf(s[j][3] - mn1));
            l0 += __uint_as_float(p0) + __uint_as_float(p1);
            l1 += __uint_as_float(p2) + __uint_as_float(p3);
            Ps[(wrow + grp    ) * 68 + j * 8 + 2 * tg    ] = p0;
            Ps[(wrow + grp    ) * 68 + j * 8 + 2 * tg + 1] = p1;
            Ps[(wrow + grp + 8) * 68 + j * 8 + 2 * tg    ] = p2;
            Ps[(wrow + grp + 8) * 68 + j * 8 + 2 * tg + 1] = p3;
        }
        if (tg == 0) {
            sm_corr[wrow + grp    ] = c0;
            sm_corr[wrow + grp + 8] = c1;
        }
        __syncthreads();

        // ---- O^T += V^T @ P^T ----
        #pragma unroll
        for (int j = 0; j < 8; j++) {
            float cc0 = sm_corr[j * 8 + 2 * tg    ];
            float cc1 = sm_corr[j * 8 + 2 * tg + 1];
            acc_o[j][0] *= cc0; acc_o[j][1] *= cc1;
            acc_o[j][2] *= cc0; acc_o[j][3] *= cc1;
        }
        #pragma unroll
        for (int kk = 0; kk < 64; kk += 8) {
            uint32_t a[4];
            a[0] = Vs[(kk + tg    ) * 68 + wrow + grp    ];
            a[1] = Vs[(kk + tg    ) * 68 + wrow + grp + 8];
            a[2] = Vs[(kk + tg + 4) * 68 + wrow + grp    ];
            a[3] = Vs[(kk + tg + 4) * 68 + wrow + grp + 8];
            #pragma unroll
            for (int j = 0; j < 8; j++) {
                uint32_t bf[2];
                bf[0] = Ps[(j * 8 + grp) * 68 + kk + tg    ];
                bf[1] = Ps[(j * 8 + grp) * 68 + kk + tg + 4];
                mma_tf32(acc_o[j], a, bf);
            }
        }
        __syncthreads();
    }

    l0 += __shfl_xor_sync(0xffffffffu, l0, 1);
    l0 += __shfl_xor_sync(0xffffffffu, l0, 2);
    l1 += __shfl_xor_sync(0xffffffffu, l1, 1);
    l1 += __shfl_xor_sync(0xffffffffu, l1, 2);
    if (tg == 0) {
        sm_l[wrow + grp    ] = l0;
        sm_l[wrow + grp + 8] = l1;
    }
    __syncthreads();

    // write O as tf32 bits (proj consumes raw)
    float* Yb = &g_Y[((size_t)(b * TT + qt * 64)) * CC + h * DD];
    #pragma unroll
    for (int j = 0; j < 8; j++) {
        int q0 = j * 8 + 2 * tg, q1 = q0 + 1;
        float i0 = 1.f / sm_l[q0];
        float i1 = 1.f / sm_l[q1];
        int d0 = wrow + grp, d1 = d0 + 8;
        Yb[q0 * CC + d0] = f2tf32f(acc_o[j][0] * i0);
        Yb[q1 * CC + d0] = f2tf32f(acc_o[j][1] * i1);
        Yb[q0 * CC + d1] = f2tf32f(acc_o[j][2] * i0);
        Yb[q1 * CC + d1] = f2tf32f(acc_o[j][3] * i1);
    }
}

// ---------------------------------------------------------------------------
extern "C" void kernel_launch(void* const* d_in, const int* in_sizes, int n_in,
                              void* d_out, int out_size)
{
    const float* x  = (const float*)d_in[0];
    const float* Wq = (const float*)d_in[1];
    const float* Wk = (const float*)d_in[2];
    const float* Wv = (const float*)d_in[3];
    const float* Wo = (const float*)d_in[4];
    float* out = (float*)d_out;

    const int smem_gemm = 3 * STG * 4;                       // 56832
    const int smem_attn = (6 * 64 * 68) * 4 + 2 * 64 * 4;    // 104960 + 512
    static bool attr_done = false;
    if (!attr_done) {
        cudaFuncSetAttribute(gemm_tf32_kernel<0>,
                             cudaFuncAttributeMaxDynamicSharedMemorySize, smem_gemm);
        cudaFuncSetAttribute(gemm_tf32_kernel<1>,
                             cudaFuncAttributeMaxDynamicSharedMemorySize, smem_gemm);
        cudaFuncSetAttribute(attn_mma_kernel,
                             cudaFuncAttributeMaxDynamicSharedMemorySize, smem_attn);
        attr_done = true;
    }

    prepass_kernel<<<192, 256>>>(Wq, Wk, Wv, Wo);

    dim3 g1(MTOT / 128, 512 / 128);
    gemm_tf32_kernel<0><<<g1, 256, smem_gemm>>>(x, nullptr);

    dim3 g2(TT / 64, HH, NB);
    attn_mma_kernel<<<g2, 128, smem_attn>>>();

    dim3 g3(MTOT / 128, CC / 128);
    gemm_tf32_kernel<1><<<g3, 256, smem_gemm>>>(nullptr, out);
}